// round 1
// baseline (speedup 1.0000x reference)
#include <cuda_runtime.h>
#include <cstdint>

// ============================================================================
// QuantizedYOLOv3Tiny — integer-code baseline
//
// Activations after quant_relu are exactly {0,2,4,6} = 2*code, code in {0..3}.
// Weights quantize to ternary {-1,0,1} * s (per-tensor s = max|w|).
// conv_out = 2*s*I where I = sum(tern*code)  (exact integer)
// next code = rint(clamp(s*I, 0, 3))         (round-half-even == jnp.round)
// Activations stored as int8 codes, NHWC. Weights repacked to [co][ky*3+kx][ci]
// int8 ternary. Conv layers use __dp4a; weights broadcast from shared memory.
// 2x2 maxpool fused into conv epilogue (max of integer accs, quantize once).
// ============================================================================

#define ALIGN16 __align__(16)

__device__ float g_scale[10];

// Quantized weights
__device__ ALIGN16 float  g_w1q[216];      // layer1 kept float: tern*s, [co][tap][ci]
__device__ ALIGN16 int8_t g_w2q[576];
__device__ ALIGN16 int8_t g_w3q[1152];
__device__ ALIGN16 int8_t g_w4q[4608];
__device__ ALIGN16 int8_t g_w5q[16128];
__device__ ALIGN16 int8_t g_w6q[52416];
__device__ ALIGN16 int8_t g_w7q[194688];
__device__ ALIGN16 int8_t g_w8q[11648];
__device__ ALIGN16 int8_t g_w9q[52416];
__device__ ALIGN16 int8_t g_w10q[28080];

// Activation code buffers (NHWC int8 codes 0..3)
__device__ ALIGN16 int8_t g_act1[16*320*320*8];
__device__ ALIGN16 int8_t g_act2[16*160*160*8];
__device__ ALIGN16 int8_t g_act3[16*80*80*16];
__device__ ALIGN16 int8_t g_act4[16*40*40*32];
__device__ ALIGN16 int8_t g_act5[16*20*20*56];
__device__ ALIGN16 int8_t g_act6[16*20*20*104];
__device__ ALIGN16 int8_t g_act7[16*20*20*208];
__device__ ALIGN16 int8_t g_act8[16*20*20*56];
__device__ ALIGN16 int8_t g_act9[16*20*20*104];

// ----------------------------------------------------------------------------
// Weight prep
// ----------------------------------------------------------------------------
__global__ void absmax10(const float* w0, const float* w1, const float* w2,
                         const float* w3, const float* w4, const float* w5,
                         const float* w6, const float* w7, const float* w8,
                         const float* w9) {
    const float* ws[10] = {w0,w1,w2,w3,w4,w5,w6,w7,w8,w9};
    const int    ns[10] = {216,576,1152,4608,16128,52416,194688,11648,52416,28080};
    int L = blockIdx.x;
    const float* w = ws[L];
    int n = ns[L];
    float m = 0.f;
    for (int i = threadIdx.x; i < n; i += blockDim.x) m = fmaxf(m, fabsf(w[i]));
    __shared__ float red[256];
    red[threadIdx.x] = m;
    __syncthreads();
    for (int s = 128; s > 0; s >>= 1) {
        if (threadIdx.x < s) red[threadIdx.x] = fmaxf(red[threadIdx.x], red[threadIdx.x + s]);
        __syncthreads();
    }
    if (threadIdx.x == 0) g_scale[L] = fmaxf(red[0], 1e-8f);
}

// layer1: keep float weights tern*s in [co][tap][ci] layout
__global__ void repack_w1(const float* __restrict__ w) {
    int i = threadIdx.x + blockIdx.x * blockDim.x;
    if (i >= 216) return;
    float s = g_scale[0];
    int co = i / 27, rem = i % 27, ci = rem / 9, t = rem % 9;
    float v = w[i] / s;
    float q = rintf(fminf(fmaxf(v, -1.f), 1.f));
    g_w1q[(co * 9 + t) * 3 + ci] = q * s;
}

// int layers: ternary int8 in [co][tap][ci]
__global__ void repack_int(const float* __restrict__ w, int8_t* __restrict__ wq,
                           int cin, int kk, int n, int sidx) {
    int i = threadIdx.x + blockIdx.x * blockDim.x;
    if (i >= n) return;
    float s = g_scale[sidx];
    int co = i / (cin * kk);
    int rem = i % (cin * kk);
    int ci = rem / kk;
    int t  = rem % kk;
    float v = w[i] / s;
    int q = (int)rintf(fminf(fmaxf(v, -1.f), 1.f));
    wq[(co * kk + t) * cin + ci] = (int8_t)q;
}

// ----------------------------------------------------------------------------
// Layer 1: float conv 3->8 on 640x640, quant_relu, fused 2x2 pool -> codes
// Input x is NCHW float. One thread = one pooled pixel, all 8 couts.
// ----------------------------------------------------------------------------
__global__ void conv1_pool(const float* __restrict__ x,
                           const float* __restrict__ wq,
                           int8_t* __restrict__ out) {
    __shared__ float ws[216];
    for (int i = threadIdx.x; i < 216; i += blockDim.x) ws[i] = wq[i];
    __syncthreads();

    int p = blockIdx.x * blockDim.x + threadIdx.x;
    if (p >= 320 * 320) return;
    int py = p / 320, px = p % 320;
    int n = blockIdx.y;

    float acc[2][2][8];
#pragma unroll
    for (int a = 0; a < 2; a++)
#pragma unroll
        for (int b = 0; b < 2; b++)
#pragma unroll
            for (int co = 0; co < 8; co++) acc[a][b][co] = 0.f;

#pragma unroll
    for (int r = 0; r < 4; r++) {
        int y = 2 * py + r - 1;
        if ((unsigned)y >= 640u) continue;
#pragma unroll
        for (int c = 0; c < 4; c++) {
            int xx = 2 * px + c - 1;
            if ((unsigned)xx >= 640u) continue;
            size_t base = ((size_t)(n * 3) * 640 + y) * 640 + xx;
            float v0 = x[base];
            float v1 = x[base + (size_t)640 * 640];
            float v2 = x[base + (size_t)2 * 640 * 640];
#pragma unroll
            for (int dy = 0; dy < 2; dy++) {
                int ky = r - dy;
                if (ky < 0 || ky > 2) continue;
#pragma unroll
                for (int dx = 0; dx < 2; dx++) {
                    int kx = c - dx;
                    if (kx < 0 || kx > 2) continue;
                    int tap = ky * 3 + kx;
#pragma unroll
                    for (int co = 0; co < 8; co++) {
                        const float* wp = &ws[(co * 9 + tap) * 3];
                        acc[dy][dx][co] += v0 * wp[0] + v1 * wp[1] + v2 * wp[2];
                    }
                }
            }
        }
    }

    size_t o = (((size_t)(n * 320 + py)) * 320 + px) * 8;
#pragma unroll
    for (int co = 0; co < 8; co++) {
        float m = fmaxf(fmaxf(acc[0][0][co], acc[0][1][co]),
                        fmaxf(acc[1][0][co], acc[1][1][co]));
        float q = fminf(fmaxf(m * 0.5f, 0.f), 3.f);
        out[o + co] = (int8_t)rintf(q);
    }
}

// ----------------------------------------------------------------------------
// Int conv 3x3 + quant_relu + fused 2x2 pool. One thread = one pooled pixel,
// 8 couts (blockIdx.z = cout group). Weights for the group in shared.
// ----------------------------------------------------------------------------
template <int CIN>
__global__ void convpool_int(const int8_t* __restrict__ in,
                             const int8_t* __restrict__ wq,
                             int sidx, int8_t* __restrict__ out,
                             int S, int COUT) {
    constexpr int W4 = CIN / 4;
    __shared__ int ws[8 * 9 * W4];
    const int* wg = (const int*)wq + blockIdx.z * (8 * 9 * W4);
    for (int i = threadIdx.x; i < 8 * 9 * W4; i += blockDim.x) ws[i] = wg[i];
    __syncthreads();

    int P = S >> 1;
    int p = blockIdx.x * blockDim.x + threadIdx.x;
    if (p >= P * P) return;
    int py = p / P, px = p % P;
    int n = blockIdx.y;

    int acc[2][2][8];
#pragma unroll
    for (int a = 0; a < 2; a++)
#pragma unroll
        for (int b = 0; b < 2; b++)
#pragma unroll
            for (int co = 0; co < 8; co++) acc[a][b][co] = 0;

#pragma unroll
    for (int r = 0; r < 4; r++) {
        int y = 2 * py + r - 1;
        if ((unsigned)y >= (unsigned)S) continue;
#pragma unroll
        for (int c = 0; c < 4; c++) {
            int xx = 2 * px + c - 1;
            if ((unsigned)xx >= (unsigned)S) continue;
            const int* ap = (const int*)(in + (((size_t)(n * S + y)) * S + xx) * CIN);
            int aw[W4];
#pragma unroll
            for (int k = 0; k < W4; k++) aw[k] = ap[k];
#pragma unroll
            for (int dy = 0; dy < 2; dy++) {
                int ky = r - dy;
                if (ky < 0 || ky > 2) continue;
#pragma unroll
                for (int dx = 0; dx < 2; dx++) {
                    int kx = c - dx;
                    if (kx < 0 || kx > 2) continue;
                    int tap = ky * 3 + kx;
#pragma unroll
                    for (int co = 0; co < 8; co++) {
                        int base = (co * 9 + tap) * W4;
#pragma unroll
                        for (int k = 0; k < W4; k++)
                            acc[dy][dx][co] = __dp4a(aw[k], ws[base + k], acc[dy][dx][co]);
                    }
                }
            }
        }
    }

    float s = g_scale[sidx];
    size_t o = (((size_t)(n * P + py)) * P + px) * COUT + blockIdx.z * 8;
#pragma unroll
    for (int co = 0; co < 8; co++) {
        int m = max(max(acc[0][0][co], acc[0][1][co]),
                    max(acc[1][0][co], acc[1][1][co]));
        float q = fminf(fmaxf(s * (float)m, 0.f), 3.f);
        out[o + co] = (int8_t)rintf(q);
    }
}

// ----------------------------------------------------------------------------
// Int conv 3x3 (no pool), 20x20, quant_relu. Thread = pixel, 8 couts.
// ----------------------------------------------------------------------------
template <int CIN>
__global__ void conv3_int(const int8_t* __restrict__ in,
                          const int8_t* __restrict__ wq,
                          int sidx, int8_t* __restrict__ out, int COUT) {
    constexpr int W4 = CIN / 4;
    __shared__ int ws[8 * 9 * W4];
    const int* wg = (const int*)wq + blockIdx.z * (8 * 9 * W4);
    for (int i = threadIdx.x; i < 8 * 9 * W4; i += blockDim.x) ws[i] = wg[i];
    __syncthreads();

    int p = blockIdx.x * blockDim.x + threadIdx.x;
    if (p >= 400) return;
    int py = p / 20, px = p % 20;
    int n = blockIdx.y;

    int acc[8] = {0, 0, 0, 0, 0, 0, 0, 0};
#pragma unroll
    for (int r = 0; r < 3; r++) {
        int y = py + r - 1;
        if ((unsigned)y >= 20u) continue;
#pragma unroll
        for (int c = 0; c < 3; c++) {
            int xx = px + c - 1;
            if ((unsigned)xx >= 20u) continue;
            const int* ap = (const int*)(in + (((size_t)((n * 20 + y) * 20 + xx))) * CIN);
            int tap = r * 3 + c;
            for (int k = 0; k < W4; k++) {
                int a = ap[k];
#pragma unroll
                for (int co = 0; co < 8; co++)
                    acc[co] = __dp4a(a, ws[(co * 9 + tap) * W4 + k], acc[co]);
            }
        }
    }

    float s = g_scale[sidx];
    size_t o = (((size_t)((n * 20 + py) * 20 + px))) * COUT + blockIdx.z * 8;
#pragma unroll
    for (int co = 0; co < 8; co++) {
        float q = fminf(fmaxf(s * (float)acc[co], 0.f), 3.f);
        out[o + co] = (int8_t)rintf(q);
    }
}

// ----------------------------------------------------------------------------
// Int conv 1x1 (layer 8), 20x20. Thread = pixel, 8 couts.
// ----------------------------------------------------------------------------
template <int CIN>
__global__ void conv1x1_int(const int8_t* __restrict__ in,
                            const int8_t* __restrict__ wq,
                            int sidx, int8_t* __restrict__ out, int COUT) {
    constexpr int W4 = CIN / 4;
    __shared__ int ws[8 * W4];
    const int* wg = (const int*)wq + blockIdx.z * (8 * W4);
    for (int i = threadIdx.x; i < 8 * W4; i += blockDim.x) ws[i] = wg[i];
    __syncthreads();

    int p = blockIdx.x * blockDim.x + threadIdx.x;
    if (p >= 400) return;
    int n = blockIdx.y;

    const int* ap = (const int*)(in + ((size_t)(n * 400 + p)) * CIN);
    int acc[8] = {0, 0, 0, 0, 0, 0, 0, 0};
    for (int k = 0; k < W4; k++) {
        int a = ap[k];
#pragma unroll
        for (int co = 0; co < 8; co++)
            acc[co] = __dp4a(a, ws[co * W4 + k], acc[co]);
    }

    float s = g_scale[sidx];
    size_t o = ((size_t)(n * 400 + p)) * COUT + blockIdx.z * 8;
#pragma unroll
    for (int co = 0; co < 8; co++) {
        float q = fminf(fmaxf(s * (float)acc[co], 0.f), 3.f);
        out[o + co] = (int8_t)rintf(q);
    }
}

// ----------------------------------------------------------------------------
// Layer 10: int conv 3x3 104->30, quant_hardtanh, fp32 NCHW output.
// Thread = pixel, blockIdx.z = cout (0..29).
// ----------------------------------------------------------------------------
__global__ void conv10_out(const int8_t* __restrict__ in,
                           const int8_t* __restrict__ wq,
                           float* __restrict__ out) {
    constexpr int W4 = 26;  // CIN=104
    __shared__ int ws[9 * W4];
    const int* wg = (const int*)wq + blockIdx.z * (9 * W4);
    for (int i = threadIdx.x; i < 9 * W4; i += blockDim.x) ws[i] = wg[i];
    __syncthreads();

    int p = blockIdx.x * blockDim.x + threadIdx.x;
    if (p >= 400) return;
    int py = p / 20, px = p % 20;
    int n = blockIdx.y;

    int acc = 0;
#pragma unroll
    for (int r = 0; r < 3; r++) {
        int y = py + r - 1;
        if ((unsigned)y >= 20u) continue;
#pragma unroll
        for (int c = 0; c < 3; c++) {
            int xx = px + c - 1;
            if ((unsigned)xx >= 20u) continue;
            const int* ap = (const int*)(in + ((size_t)((n * 20 + y) * 20 + xx)) * 104);
            int tap = r * 3 + c;
#pragma unroll
            for (int k = 0; k < W4; k++)
                acc = __dp4a(ap[k], ws[tap * W4 + k], acc);
        }
    }

    float s = g_scale[9];
    float v = 2.f * s * (float)acc;          // conv output value
    float t = fminf(fmaxf(v, 0.f), 1.f);     // hardtanh clip [0,1]
    float o = rintf(t * 255.f) / 255.f;      // 8-bit quant
    out[((size_t)(n * 30 + blockIdx.z)) * 400 + p] = o;
}

// ----------------------------------------------------------------------------
// Launch
// ----------------------------------------------------------------------------
extern "C" void kernel_launch(void* const* d_in, const int* in_sizes, int n_in,
                              void* d_out, int out_size) {
    const float* x = (const float*)d_in[0];
    const float* w[10];
    for (int i = 0; i < 10; i++) w[i] = (const float*)d_in[1 + i];

    void *p_w1q, *p_w2, *p_w3, *p_w4, *p_w5, *p_w6, *p_w7, *p_w8, *p_w9, *p_w10;
    void *p_a1, *p_a2, *p_a3, *p_a4, *p_a5, *p_a6, *p_a7, *p_a8, *p_a9;
    cudaGetSymbolAddress(&p_w1q, g_w1q);
    cudaGetSymbolAddress(&p_w2, g_w2q);
    cudaGetSymbolAddress(&p_w3, g_w3q);
    cudaGetSymbolAddress(&p_w4, g_w4q);
    cudaGetSymbolAddress(&p_w5, g_w5q);
    cudaGetSymbolAddress(&p_w6, g_w6q);
    cudaGetSymbolAddress(&p_w7, g_w7q);
    cudaGetSymbolAddress(&p_w8, g_w8q);
    cudaGetSymbolAddress(&p_w9, g_w9q);
    cudaGetSymbolAddress(&p_w10, g_w10q);
    cudaGetSymbolAddress(&p_a1, g_act1);
    cudaGetSymbolAddress(&p_a2, g_act2);
    cudaGetSymbolAddress(&p_a3, g_act3);
    cudaGetSymbolAddress(&p_a4, g_act4);
    cudaGetSymbolAddress(&p_a5, g_act5);
    cudaGetSymbolAddress(&p_a6, g_act6);
    cudaGetSymbolAddress(&p_a7, g_act7);
    cudaGetSymbolAddress(&p_a8, g_act8);
    cudaGetSymbolAddress(&p_a9, g_act9);

    // Weight prep
    absmax10<<<10, 256>>>(w[0], w[1], w[2], w[3], w[4], w[5], w[6], w[7], w[8], w[9]);
    repack_w1<<<1, 256>>>(w[0]);
    repack_int<<<(576 + 255) / 256, 256>>>(w[1], (int8_t*)p_w2, 8, 9, 576, 1);
    repack_int<<<(1152 + 255) / 256, 256>>>(w[2], (int8_t*)p_w3, 8, 9, 1152, 2);
    repack_int<<<(4608 + 255) / 256, 256>>>(w[3], (int8_t*)p_w4, 16, 9, 4608, 3);
    repack_int<<<(16128 + 255) / 256, 256>>>(w[4], (int8_t*)p_w5, 32, 9, 16128, 4);
    repack_int<<<(52416 + 255) / 256, 256>>>(w[5], (int8_t*)p_w6, 56, 9, 52416, 5);
    repack_int<<<(194688 + 255) / 256, 256>>>(w[6], (int8_t*)p_w7, 104, 9, 194688, 6);
    repack_int<<<(11648 + 255) / 256, 256>>>(w[7], (int8_t*)p_w8, 208, 1, 11648, 7);
    repack_int<<<(52416 + 255) / 256, 256>>>(w[8], (int8_t*)p_w9, 56, 9, 52416, 8);
    repack_int<<<(28080 + 255) / 256, 256>>>(w[9], (int8_t*)p_w10, 104, 9, 28080, 9);

    // Layer 1: float conv + quant + pool -> codes (16,320,320,8)
    conv1_pool<<<dim3(800, 16), 128>>>(x, (const float*)p_w1q, (int8_t*)p_a1);

    // Layer 2: 8->8, S=320 -> P=160
    convpool_int<8><<<dim3(200, 16, 1), 128>>>((const int8_t*)p_a1, (const int8_t*)p_w2, 1,
                                               (int8_t*)p_a2, 320, 8);
    // Layer 3: 8->16, S=160 -> P=80
    convpool_int<8><<<dim3(50, 16, 2), 128>>>((const int8_t*)p_a2, (const int8_t*)p_w3, 2,
                                              (int8_t*)p_a3, 160, 16);
    // Layer 4: 16->32, S=80 -> P=40
    convpool_int<16><<<dim3(13, 16, 4), 128>>>((const int8_t*)p_a3, (const int8_t*)p_w4, 3,
                                               (int8_t*)p_a4, 80, 32);
    // Layer 5: 32->56, S=40 -> P=20
    convpool_int<32><<<dim3(4, 16, 7), 128>>>((const int8_t*)p_a4, (const int8_t*)p_w5, 4,
                                              (int8_t*)p_a5, 40, 56);
    // Layer 6: 56->104, 20x20
    conv3_int<56><<<dim3(4, 16, 13), 128>>>((const int8_t*)p_a5, (const int8_t*)p_w6, 5,
                                            (int8_t*)p_a6, 104);
    // Layer 7: 104->208, 20x20
    conv3_int<104><<<dim3(4, 16, 26), 128>>>((const int8_t*)p_a6, (const int8_t*)p_w7, 6,
                                             (int8_t*)p_a7, 208);
    // Layer 8: 1x1 208->56
    conv1x1_int<208><<<dim3(4, 16, 7), 128>>>((const int8_t*)p_a7, (const int8_t*)p_w8, 7,
                                              (int8_t*)p_a8, 56);
    // Layer 9: 56->104, 20x20
    conv3_int<56><<<dim3(4, 16, 13), 128>>>((const int8_t*)p_a8, (const int8_t*)p_w9, 8,
                                            (int8_t*)p_a9, 104);
    // Layer 10: 104->30, hardtanh, fp32 NCHW out
    conv10_out<<<dim3(4, 16, 30), 128>>>((const int8_t*)p_a9, (const int8_t*)p_w10,
                                         (float*)d_out);
}

// round 2
// speedup vs baseline: 1.6254x; 1.6254x over previous
#include <cuda_runtime.h>
#include <cstdint>

// ============================================================================
// QuantizedYOLOv3Tiny — round 2
// - single fused weight-prep kernel (absmax + ternary repack, 1 block/layer)
// - conv1: smem input tile + register weights + fma.rn.f32x2 packed math
// - int layers: dp4a, int2 activation loads, packed code stores
// Codes: act = 2*code, code in {0..3}; weights ternary*s. All int math exact.
// ============================================================================

#define ALIGN16 __align__(16)

__device__ float g_scale[10];

__device__ ALIGN16 float  g_w1q[216];      // layer1: tern*s, layout [tap][ci][co] (co contiguous, 8)
__device__ ALIGN16 int8_t g_w2q[576];
__device__ ALIGN16 int8_t g_w3q[1152];
__device__ ALIGN16 int8_t g_w4q[4608];
__device__ ALIGN16 int8_t g_w5q[16128];
__device__ ALIGN16 int8_t g_w6q[52416];
__device__ ALIGN16 int8_t g_w7q[194688];
__device__ ALIGN16 int8_t g_w8q[11648];
__device__ ALIGN16 int8_t g_w9q[52416];
__device__ ALIGN16 int8_t g_w10q[28080];

__device__ ALIGN16 int8_t g_act1[16*320*320*8];
__device__ ALIGN16 int8_t g_act2[16*160*160*8];
__device__ ALIGN16 int8_t g_act3[16*80*80*16];
__device__ ALIGN16 int8_t g_act4[16*40*40*32];
__device__ ALIGN16 int8_t g_act5[16*20*20*56];
__device__ ALIGN16 int8_t g_act6[16*20*20*104];
__device__ ALIGN16 int8_t g_act7[16*20*20*208];
__device__ ALIGN16 int8_t g_act8[16*20*20*56];
__device__ ALIGN16 int8_t g_act9[16*20*20*104];

// ----------------------------------------------------------------------------
// Fused weight prep: block L does absmax reduce + repack for layer L.
// ----------------------------------------------------------------------------
__global__ void prep_all(const float* w0, const float* w1, const float* w2,
                         const float* w3, const float* w4, const float* w5,
                         const float* w6, const float* w7, const float* w8,
                         const float* w9) {
    const float* ws[10] = {w0,w1,w2,w3,w4,w5,w6,w7,w8,w9};
    const int    ns[10] = {216,576,1152,4608,16128,52416,194688,11648,52416,28080};
    const int  cins[10] = {3,8,8,16,32,56,104,208,56,104};
    const int   kks[10] = {9,9,9,9,9,9,9,1,9,9};
    int8_t* wqs[10] = {nullptr, g_w2q, g_w3q, g_w4q, g_w5q, g_w6q,
                       g_w7q, g_w8q, g_w9q, g_w10q};

    int L = blockIdx.x;
    const float* w = ws[L];
    int n = ns[L];
    int tid = threadIdx.x;

    // absmax (float4 loads; all n divisible by 4, pointers 256B aligned)
    float m = 0.f;
    const float4* w4p = (const float4*)w;
    int n4 = n >> 2;
    for (int i = tid; i < n4; i += blockDim.x) {
        float4 v = w4p[i];
        m = fmaxf(m, fmaxf(fmaxf(fabsf(v.x), fabsf(v.y)),
                           fmaxf(fabsf(v.z), fabsf(v.w))));
    }
    __shared__ float red[1024];
    red[tid] = m;
    __syncthreads();
    for (int s = 512; s > 0; s >>= 1) {
        if (tid < s) red[tid] = fmaxf(red[tid], red[tid + s]);
        __syncthreads();
    }
    float s = fmaxf(red[0], 1e-8f);
    if (tid == 0) g_scale[L] = s;

    if (L == 0) {
        // layout [tap][ci][co]: pairs (2j,2j+1) contiguous for f32x2 weight regs
        for (int i = tid; i < 216; i += blockDim.x) {
            int co = i / 27, rem = i % 27, ci = rem / 9, t = rem % 9;
            float v = w[i] / s;
            float q = rintf(fminf(fmaxf(v, -1.f), 1.f));
            g_w1q[(t * 3 + ci) * 8 + co] = q * s;
        }
    } else {
        int cin = cins[L], kk = kks[L];
        int8_t* wq = wqs[L];
        for (int i = tid; i < n; i += blockDim.x) {
            int co = i / (cin * kk);
            int rem = i % (cin * kk);
            int ci = rem / kk;
            int t  = rem % kk;
            float v = w[i] / s;
            int q = (int)rintf(fminf(fmaxf(v, -1.f), 1.f));
            wq[(co * kk + t) * cin + ci] = (int8_t)q;
        }
    }
}

// ----------------------------------------------------------------------------
// f32x2 helpers
// ----------------------------------------------------------------------------
__device__ __forceinline__ void ffma2(unsigned long long& d,
                                      unsigned long long a,
                                      unsigned long long b) {
    asm("fma.rn.f32x2 %0, %1, %2, %0;" : "+l"(d) : "l"(a), "l"(b));
}
__device__ __forceinline__ unsigned long long packdup(float v) {
    unsigned long long r;
    uint32_t b = __float_as_uint(v);
    asm("mov.b64 %0, {%1, %1};" : "=l"(r) : "r"(b));
    return r;
}
__device__ __forceinline__ void unpack2(unsigned long long v, float& lo, float& hi) {
    uint32_t a, b;
    asm("mov.b64 {%0, %1}, %2;" : "=r"(a), "=r"(b) : "l"(v));
    lo = __uint_as_float(a);
    hi = __uint_as_float(b);
}

// ----------------------------------------------------------------------------
// Layer 1: float conv 3->8 @640x640 + quant_relu + 2x2 pool -> codes.
// Block: 256 threads = 64 pooled pixels (16x4 tile) x 4 cout-pairs.
// Input tile in smem (zero-padded borders); weights in registers (27 f32x2).
// ----------------------------------------------------------------------------
__global__ __launch_bounds__(256) void conv1_pool(const float* __restrict__ x,
                                                  int8_t* __restrict__ out) {
    __shared__ float s_in[3][10][36];

    const int tid = threadIdx.x;
    const int pair = tid & 3;
    const int q = tid >> 2;          // 0..63
    const int tx = q & 15, ty = q >> 4;
    const int n = blockIdx.z;
    const int px0 = blockIdx.x * 16, py0 = blockIdx.y * 4;

    // cooperative tile load: region [2*py0-1 .. 2*py0+8] x [2*px0-1 .. 2*px0+32]
    for (int i = tid; i < 3 * 10 * 34; i += 256) {
        int ch = i / 340, rem = i % 340, row = rem / 34, col = rem % 34;
        int gx = 2 * px0 - 1 + col;
        int gy = 2 * py0 - 1 + row;
        float v = 0.f;
        if ((unsigned)gx < 640u && (unsigned)gy < 640u)
            v = x[((size_t)(n * 3 + ch) * 640 + gy) * 640 + gx];
        s_in[ch][row][col] = v;
    }

    // weight registers: 27 f32x2 (this thread's cout pair)
    unsigned long long wreg[27];
    const unsigned long long* wsrc = (const unsigned long long*)g_w1q;
#pragma unroll
    for (int i = 0; i < 27; i++) wreg[i] = wsrc[i * 4 + pair];

    __syncthreads();

    unsigned long long acc[2][2] = {{0ull, 0ull}, {0ull, 0ull}};

#pragma unroll
    for (int r = 0; r < 4; r++) {
#pragma unroll
        for (int c = 0; c < 4; c++) {
            int row = 2 * ty + r, col = 2 * tx + c;
            unsigned long long vv0 = packdup(s_in[0][row][col]);
            unsigned long long vv1 = packdup(s_in[1][row][col]);
            unsigned long long vv2 = packdup(s_in[2][row][col]);
#pragma unroll
            for (int dy = 0; dy < 2; dy++) {
                int ky = r - dy;
                if (ky < 0 || ky > 2) continue;
#pragma unroll
                for (int dx = 0; dx < 2; dx++) {
                    int kx = c - dx;
                    if (kx < 0 || kx > 2) continue;
                    int tap = ky * 3 + kx;
                    ffma2(acc[dy][dx], vv0, wreg[tap * 3 + 0]);
                    ffma2(acc[dy][dx], vv1, wreg[tap * 3 + 1]);
                    ffma2(acc[dy][dx], vv2, wreg[tap * 3 + 2]);
                }
            }
        }
    }

    float l00, h00, l01, h01, l10, h10, l11, h11;
    unpack2(acc[0][0], l00, h00);
    unpack2(acc[0][1], l01, h01);
    unpack2(acc[1][0], l10, h10);
    unpack2(acc[1][1], l11, h11);
    float m0 = fmaxf(fmaxf(l00, l01), fmaxf(l10, l11));
    float m1 = fmaxf(fmaxf(h00, h01), fmaxf(h10, h11));
    int c0 = (int)rintf(fminf(fmaxf(m0 * 0.5f, 0.f), 3.f));
    int c1 = (int)rintf(fminf(fmaxf(m1 * 0.5f, 0.f), 3.f));
    unsigned short pk = (unsigned short)(c0 | (c1 << 8));

    size_t o = ((size_t)n * 102400 + (size_t)(py0 + ty) * 320 + (px0 + tx)) * 8
               + (size_t)pair * 2;
    *(unsigned short*)(out + o) = pk;
}

// ----------------------------------------------------------------------------
// Int conv 3x3 + quant_relu + 2x2 pool. Thread = pooled pixel x 8 couts.
// int2 activation loads, packed uint2 store.
// ----------------------------------------------------------------------------
template <int CIN>
__global__ __launch_bounds__(128) void convpool_int(const int8_t* __restrict__ in,
                                                    const int8_t* __restrict__ wq,
                                                    int sidx, int8_t* __restrict__ out,
                                                    int S, int COUT) {
    constexpr int W4 = CIN / 4;
    constexpr int W8 = W4 / 2;
    __shared__ int ws[8 * 9 * W4];
    const int* wg = (const int*)wq + blockIdx.z * (8 * 9 * W4);
    for (int i = threadIdx.x; i < 8 * 9 * W4; i += blockDim.x) ws[i] = wg[i];
    __syncthreads();

    int P = S >> 1;
    int p = blockIdx.x * blockDim.x + threadIdx.x;
    if (p >= P * P) return;
    int py = p / P, px = p % P;
    int n = blockIdx.y;

    int acc[2][2][8];
#pragma unroll
    for (int a = 0; a < 2; a++)
#pragma unroll
        for (int b = 0; b < 2; b++)
#pragma unroll
            for (int co = 0; co < 8; co++) acc[a][b][co] = 0;

#pragma unroll
    for (int r = 0; r < 4; r++) {
        int y = 2 * py + r - 1;
        if ((unsigned)y >= (unsigned)S) continue;
#pragma unroll
        for (int c = 0; c < 4; c++) {
            int xx = 2 * px + c - 1;
            if ((unsigned)xx >= (unsigned)S) continue;
            const int2* ap = (const int2*)(in + (((size_t)(n * S + y)) * S + xx) * CIN);
            int aw[W4];
#pragma unroll
            for (int k = 0; k < W8; k++) {
                int2 v = ap[k];
                aw[2 * k] = v.x;
                aw[2 * k + 1] = v.y;
            }
#pragma unroll
            for (int dy = 0; dy < 2; dy++) {
                int ky = r - dy;
                if (ky < 0 || ky > 2) continue;
#pragma unroll
                for (int dx = 0; dx < 2; dx++) {
                    int kx = c - dx;
                    if (kx < 0 || kx > 2) continue;
                    int tap = ky * 3 + kx;
#pragma unroll
                    for (int co = 0; co < 8; co++) {
                        int base = (co * 9 + tap) * W4;
#pragma unroll
                        for (int k = 0; k < W4; k++)
                            acc[dy][dx][co] = __dp4a(aw[k], ws[base + k], acc[dy][dx][co]);
                    }
                }
            }
        }
    }

    float s = g_scale[sidx];
    uint32_t b0 = 0, b1 = 0;
#pragma unroll
    for (int co = 0; co < 8; co++) {
        int m = max(max(acc[0][0][co], acc[0][1][co]),
                    max(acc[1][0][co], acc[1][1][co]));
        uint32_t code = (uint32_t)(int)rintf(fminf(fmaxf(s * (float)m, 0.f), 3.f));
        if (co < 4) b0 |= code << (co * 8);
        else        b1 |= code << ((co - 4) * 8);
    }
    size_t o = (((size_t)(n * P + py)) * P + px) * COUT + blockIdx.z * 8;
    *(uint2*)(out + o) = make_uint2(b0, b1);
}

// ----------------------------------------------------------------------------
// Int conv 3x3 (no pool) on 20x20, 4 couts/thread.
// ----------------------------------------------------------------------------
template <int CIN>
__global__ __launch_bounds__(128) void conv3_int4(const int8_t* __restrict__ in,
                                                  const int8_t* __restrict__ wq,
                                                  int sidx, int8_t* __restrict__ out,
                                                  int COUT) {
    constexpr int W4 = CIN / 4;
    constexpr int W8 = W4 / 2;
    __shared__ int ws[4 * 9 * W4];
    const int* wg = (const int*)wq + blockIdx.z * (4 * 9 * W4);
    for (int i = threadIdx.x; i < 4 * 9 * W4; i += blockDim.x) ws[i] = wg[i];
    __syncthreads();

    int p = blockIdx.x * blockDim.x + threadIdx.x;
    if (p >= 400) return;
    int py = p / 20, px = p % 20;
    int n = blockIdx.y;

    int acc[4] = {0, 0, 0, 0};
#pragma unroll
    for (int r = 0; r < 3; r++) {
        int y = py + r - 1;
        if ((unsigned)y >= 20u) continue;
#pragma unroll
        for (int c = 0; c < 3; c++) {
            int xx = px + c - 1;
            if ((unsigned)xx >= 20u) continue;
            const int2* ap = (const int2*)(in + ((size_t)((n * 20 + y) * 20 + xx)) * CIN);
            int tap = r * 3 + c;
#pragma unroll
            for (int k = 0; k < W8; k++) {
                int2 a = ap[k];
#pragma unroll
                for (int co = 0; co < 4; co++) {
                    acc[co] = __dp4a(a.x, ws[(co * 9 + tap) * W4 + 2 * k], acc[co]);
                    acc[co] = __dp4a(a.y, ws[(co * 9 + tap) * W4 + 2 * k + 1], acc[co]);
                }
            }
        }
    }

    float s = g_scale[sidx];
    uint32_t b = 0;
#pragma unroll
    for (int co = 0; co < 4; co++) {
        uint32_t code = (uint32_t)(int)rintf(fminf(fmaxf(s * (float)acc[co], 0.f), 3.f));
        b |= code << (co * 8);
    }
    size_t o = ((size_t)((n * 20 + py) * 20 + px)) * COUT + blockIdx.z * 4;
    *(uint32_t*)(out + o) = b;
}

// ----------------------------------------------------------------------------
// Int conv 1x1 on 20x20, 4 couts/thread.
// ----------------------------------------------------------------------------
template <int CIN>
__global__ __launch_bounds__(128) void conv1x1_int4(const int8_t* __restrict__ in,
                                                    const int8_t* __restrict__ wq,
                                                    int sidx, int8_t* __restrict__ out,
                                                    int COUT) {
    constexpr int W4 = CIN / 4;
    constexpr int W8 = W4 / 2;
    __shared__ int ws[4 * W4];
    const int* wg = (const int*)wq + blockIdx.z * (4 * W4);
    for (int i = threadIdx.x; i < 4 * W4; i += blockDim.x) ws[i] = wg[i];
    __syncthreads();

    int p = blockIdx.x * blockDim.x + threadIdx.x;
    if (p >= 400) return;
    int n = blockIdx.y;

    const int2* ap = (const int2*)(in + ((size_t)(n * 400 + p)) * CIN);
    int acc[4] = {0, 0, 0, 0};
#pragma unroll
    for (int k = 0; k < W8; k++) {
        int2 a = ap[k];
#pragma unroll
        for (int co = 0; co < 4; co++) {
            acc[co] = __dp4a(a.x, ws[co * W4 + 2 * k], acc[co]);
            acc[co] = __dp4a(a.y, ws[co * W4 + 2 * k + 1], acc[co]);
        }
    }

    float s = g_scale[sidx];
    uint32_t b = 0;
#pragma unroll
    for (int co = 0; co < 4; co++) {
        uint32_t code = (uint32_t)(int)rintf(fminf(fmaxf(s * (float)acc[co], 0.f), 3.f));
        b |= code << (co * 8);
    }
    size_t o = ((size_t)(n * 400 + p)) * COUT + blockIdx.z * 4;
    *(uint32_t*)(out + o) = b;
}

// ----------------------------------------------------------------------------
// Layer 10: int conv 3x3 104->30 + quant_hardtanh, fp32 NCHW out.
// ----------------------------------------------------------------------------
__global__ __launch_bounds__(128) void conv10_out(const int8_t* __restrict__ in,
                                                  const int8_t* __restrict__ wq,
                                                  float* __restrict__ out) {
    constexpr int W4 = 26;
    constexpr int W8 = 13;
    __shared__ int ws[9 * W4];
    const int* wg = (const int*)wq + blockIdx.z * (9 * W4);
    for (int i = threadIdx.x; i < 9 * W4; i += blockDim.x) ws[i] = wg[i];
    __syncthreads();

    int p = blockIdx.x * blockDim.x + threadIdx.x;
    if (p >= 400) return;
    int py = p / 20, px = p % 20;
    int n = blockIdx.y;

    int acc = 0;
#pragma unroll
    for (int r = 0; r < 3; r++) {
        int y = py + r - 1;
        if ((unsigned)y >= 20u) continue;
#pragma unroll
        for (int c = 0; c < 3; c++) {
            int xx = px + c - 1;
            if ((unsigned)xx >= 20u) continue;
            const int2* ap = (const int2*)(in + ((size_t)((n * 20 + y) * 20 + xx)) * 104);
            int tap = r * 3 + c;
#pragma unroll
            for (int k = 0; k < W8; k++) {
                int2 a = ap[k];
                acc = __dp4a(a.x, ws[tap * W4 + 2 * k], acc);
                acc = __dp4a(a.y, ws[tap * W4 + 2 * k + 1], acc);
            }
        }
    }

    float s = g_scale[9];
    float v = 2.f * s * (float)acc;
    float t = fminf(fmaxf(v, 0.f), 1.f);
    float o = rintf(t * 255.f) * (1.f / 255.f);
    out[((size_t)(n * 30 + blockIdx.z)) * 400 + p] = o;
}

// ----------------------------------------------------------------------------
// Launch
// ----------------------------------------------------------------------------
extern "C" void kernel_launch(void* const* d_in, const int* in_sizes, int n_in,
                              void* d_out, int out_size) {
    const float* x = (const float*)d_in[0];
    const float* w[10];
    for (int i = 0; i < 10; i++) w[i] = (const float*)d_in[1 + i];

    void *p_w2, *p_w3, *p_w4, *p_w5, *p_w6, *p_w7, *p_w8, *p_w9, *p_w10;
    void *p_a1, *p_a2, *p_a3, *p_a4, *p_a5, *p_a6, *p_a7, *p_a8, *p_a9;
    cudaGetSymbolAddress(&p_w2, g_w2q);
    cudaGetSymbolAddress(&p_w3, g_w3q);
    cudaGetSymbolAddress(&p_w4, g_w4q);
    cudaGetSymbolAddress(&p_w5, g_w5q);
    cudaGetSymbolAddress(&p_w6, g_w6q);
    cudaGetSymbolAddress(&p_w7, g_w7q);
    cudaGetSymbolAddress(&p_w8, g_w8q);
    cudaGetSymbolAddress(&p_w9, g_w9q);
    cudaGetSymbolAddress(&p_w10, g_w10q);
    cudaGetSymbolAddress(&p_a1, g_act1);
    cudaGetSymbolAddress(&p_a2, g_act2);
    cudaGetSymbolAddress(&p_a3, g_act3);
    cudaGetSymbolAddress(&p_a4, g_act4);
    cudaGetSymbolAddress(&p_a5, g_act5);
    cudaGetSymbolAddress(&p_a6, g_act6);
    cudaGetSymbolAddress(&p_a7, g_act7);
    cudaGetSymbolAddress(&p_a8, g_act8);
    cudaGetSymbolAddress(&p_a9, g_act9);

    prep_all<<<10, 1024>>>(w[0], w[1], w[2], w[3], w[4], w[5], w[6], w[7], w[8], w[9]);

    conv1_pool<<<dim3(20, 80, 16), 256>>>(x, (int8_t*)p_a1);

    convpool_int<8><<<dim3(200, 16, 1), 128>>>((const int8_t*)p_a1, (const int8_t*)p_w2, 1,
                                               (int8_t*)p_a2, 320, 8);
    convpool_int<8><<<dim3(50, 16, 2), 128>>>((const int8_t*)p_a2, (const int8_t*)p_w3, 2,
                                              (int8_t*)p_a3, 160, 16);
    convpool_int<16><<<dim3(13, 16, 4), 128>>>((const int8_t*)p_a3, (const int8_t*)p_w4, 3,
                                               (int8_t*)p_a4, 80, 32);
    convpool_int<32><<<dim3(4, 16, 7), 128>>>((const int8_t*)p_a4, (const int8_t*)p_w5, 4,
                                              (int8_t*)p_a5, 40, 56);
    conv3_int4<56><<<dim3(4, 16, 26), 128>>>((const int8_t*)p_a5, (const int8_t*)p_w6, 5,
                                             (int8_t*)p_a6, 104);
    conv3_int4<104><<<dim3(4, 16, 52), 128>>>((const int8_t*)p_a6, (const int8_t*)p_w7, 6,
                                              (int8_t*)p_a7, 208);
    conv1x1_int4<208><<<dim3(4, 16, 14), 128>>>((const int8_t*)p_a7, (const int8_t*)p_w8, 7,
                                                (int8_t*)p_a8, 56);
    conv3_int4<56><<<dim3(4, 16, 26), 128>>>((const int8_t*)p_a8, (const int8_t*)p_w9, 8,
                                             (int8_t*)p_a9, 104);
    conv10_out<<<dim3(4, 16, 30), 128>>>((const int8_t*)p_a9, (const int8_t*)p_w10,
                                         (float*)d_out);
}

// round 3
// speedup vs baseline: 1.6618x; 1.0224x over previous
#include <cuda_runtime.h>
#include <cstdint>

// ============================================================================
// QuantizedYOLOv3Tiny — round 3
// Activations: planar code layout, uint32 word = 4 channels of one pixel,
//   arranged [n][cgroup][H*W]. Codes in {0..3}, act value = 2*code.
// Weights: ternary {-1,0,1} int8, [co][tap][ci] (word k = 4 ci).
// Int convs: 4 output columns per thread x NCO couts; weight smem word reused
//   across the 4 columns (4 dp4a per LDS). Activation window = 6 consecutive
//   words per (row,k) -> coalesced.
// ============================================================================

#define ALIGN16 __align__(16)

__device__ float g_scale[10];

__device__ ALIGN16 float  g_w1q[216];      // layer1: tern*s, [tap][ci][co]
__device__ ALIGN16 int8_t g_w2q[576];
__device__ ALIGN16 int8_t g_w3q[1152];
__device__ ALIGN16 int8_t g_w4q[4608];
__device__ ALIGN16 int8_t g_w5q[16128];
__device__ ALIGN16 int8_t g_w6q[52416];
__device__ ALIGN16 int8_t g_w7q[194688];
__device__ ALIGN16 int8_t g_w8q[11648];
__device__ ALIGN16 int8_t g_w9q[52416];
__device__ ALIGN16 int8_t g_w10q[28080];

// Activation planar word buffers
__device__ ALIGN16 uint32_t g_act1[16*2*320*320];
__device__ ALIGN16 uint32_t g_act2[16*2*160*160];
__device__ ALIGN16 uint32_t g_act3[16*4*80*80];
__device__ ALIGN16 uint32_t g_act4[16*8*40*40];
__device__ ALIGN16 uint32_t g_act5[16*14*20*20];
__device__ ALIGN16 uint32_t g_act6[16*26*20*20];
__device__ ALIGN16 uint32_t g_act7[16*52*20*20];
__device__ ALIGN16 uint32_t g_act8[16*14*20*20];
__device__ ALIGN16 uint32_t g_act9[16*26*20*20];

// ----------------------------------------------------------------------------
// Fused weight prep: block L = absmax reduce + ternary repack for layer L.
// ----------------------------------------------------------------------------
__global__ void prep_all(const float* w0, const float* w1, const float* w2,
                         const float* w3, const float* w4, const float* w5,
                         const float* w6, const float* w7, const float* w8,
                         const float* w9) {
    const float* ws[10] = {w0,w1,w2,w3,w4,w5,w6,w7,w8,w9};
    const int    ns[10] = {216,576,1152,4608,16128,52416,194688,11648,52416,28080};
    const int  cins[10] = {3,8,8,16,32,56,104,208,56,104};
    const int   kks[10] = {9,9,9,9,9,9,9,1,9,9};
    int8_t* wqs[10] = {nullptr, g_w2q, g_w3q, g_w4q, g_w5q, g_w6q,
                       g_w7q, g_w8q, g_w9q, g_w10q};

    int L = blockIdx.x;
    const float* w = ws[L];
    int n = ns[L];
    int tid = threadIdx.x;

    float m = 0.f;
    const float4* w4p = (const float4*)w;
    int n4 = n >> 2;
    for (int i = tid; i < n4; i += blockDim.x) {
        float4 v = w4p[i];
        m = fmaxf(m, fmaxf(fmaxf(fabsf(v.x), fabsf(v.y)),
                           fmaxf(fabsf(v.z), fabsf(v.w))));
    }
    __shared__ float red[1024];
    red[tid] = m;
    __syncthreads();
    for (int s = 512; s > 0; s >>= 1) {
        if (tid < s) red[tid] = fmaxf(red[tid], red[tid + s]);
        __syncthreads();
    }
    float s = fmaxf(red[0], 1e-8f);
    if (tid == 0) g_scale[L] = s;

    if (L == 0) {
        for (int i = tid; i < 216; i += blockDim.x) {
            int co = i / 27, rem = i % 27, ci = rem / 9, t = rem % 9;
            float v = w[i] / s;
            float q = rintf(fminf(fmaxf(v, -1.f), 1.f));
            g_w1q[(t * 3 + ci) * 8 + co] = q * s;
        }
    } else {
        int cin = cins[L], kk = kks[L];
        int8_t* wq = wqs[L];
        for (int i = tid; i < n; i += blockDim.x) {
            int co = i / (cin * kk);
            int rem = i % (cin * kk);
            int ci = rem / kk;
            int t  = rem % kk;
            float v = w[i] / s;
            int q = (int)rintf(fminf(fmaxf(v, -1.f), 1.f));
            wq[(co * kk + t) * cin + ci] = (int8_t)q;
        }
    }
}

// ----------------------------------------------------------------------------
// f32x2 helpers (conv1)
// ----------------------------------------------------------------------------
__device__ __forceinline__ void ffma2(unsigned long long& d,
                                      unsigned long long a,
                                      unsigned long long b) {
    asm("fma.rn.f32x2 %0, %1, %2, %0;" : "+l"(d) : "l"(a), "l"(b));
}
__device__ __forceinline__ unsigned long long packdup(float v) {
    unsigned long long r;
    uint32_t b = __float_as_uint(v);
    asm("mov.b64 %0, {%1, %1};" : "=l"(r) : "r"(b));
    return r;
}
__device__ __forceinline__ void unpack2(unsigned long long v, float& lo, float& hi) {
    uint32_t a, b;
    asm("mov.b64 {%0, %1}, %2;" : "=r"(a), "=r"(b) : "l"(v));
    lo = __uint_as_float(a);
    hi = __uint_as_float(b);
}

// ----------------------------------------------------------------------------
// Layer 1: float conv 3->8 @640x640 + quant_relu + 2x2 pool -> planar codes.
// 256 threads = 64 pooled pixels x 4 cout-pairs. Epilogue packs words via shfl.
// ----------------------------------------------------------------------------
__global__ __launch_bounds__(256) void conv1_pool(const float* __restrict__ x,
                                                  uint32_t* __restrict__ out) {
    __shared__ float s_in[3][10][36];

    const int tid = threadIdx.x;
    const int pair = tid & 3;
    const int q = tid >> 2;
    const int tx = q & 15, ty = q >> 4;
    const int n = blockIdx.z;
    const int px0 = blockIdx.x * 16, py0 = blockIdx.y * 4;

    for (int i = tid; i < 3 * 10 * 34; i += 256) {
        int ch = i / 340, rem = i % 340, row = rem / 34, col = rem % 34;
        int gx = 2 * px0 - 1 + col;
        int gy = 2 * py0 - 1 + row;
        float v = 0.f;
        if ((unsigned)gx < 640u && (unsigned)gy < 640u)
            v = x[((size_t)(n * 3 + ch) * 640 + gy) * 640 + gx];
        s_in[ch][row][col] = v;
    }

    unsigned long long wreg[27];
    const unsigned long long* wsrc = (const unsigned long long*)g_w1q;
#pragma unroll
    for (int i = 0; i < 27; i++) wreg[i] = wsrc[i * 4 + pair];

    __syncthreads();

    unsigned long long acc[2][2] = {{0ull, 0ull}, {0ull, 0ull}};

#pragma unroll
    for (int r = 0; r < 4; r++) {
#pragma unroll
        for (int c = 0; c < 4; c++) {
            int row = 2 * ty + r, col = 2 * tx + c;
            unsigned long long vv0 = packdup(s_in[0][row][col]);
            unsigned long long vv1 = packdup(s_in[1][row][col]);
            unsigned long long vv2 = packdup(s_in[2][row][col]);
#pragma unroll
            for (int dy = 0; dy < 2; dy++) {
                int ky = r - dy;
                if (ky < 0 || ky > 2) continue;
#pragma unroll
                for (int dx = 0; dx < 2; dx++) {
                    int kx = c - dx;
                    if (kx < 0 || kx > 2) continue;
                    int tap = ky * 3 + kx;
                    ffma2(acc[dy][dx], vv0, wreg[tap * 3 + 0]);
                    ffma2(acc[dy][dx], vv1, wreg[tap * 3 + 1]);
                    ffma2(acc[dy][dx], vv2, wreg[tap * 3 + 2]);
                }
            }
        }
    }

    float l00, h00, l01, h01, l10, h10, l11, h11;
    unpack2(acc[0][0], l00, h00);
    unpack2(acc[0][1], l01, h01);
    unpack2(acc[1][0], l10, h10);
    unpack2(acc[1][1], l11, h11);
    float m0 = fmaxf(fmaxf(l00, l01), fmaxf(l10, l11));
    float m1 = fmaxf(fmaxf(h00, h01), fmaxf(h10, h11));
    uint32_t c0 = (uint32_t)(int)rintf(fminf(fmaxf(m0 * 0.5f, 0.f), 3.f));
    uint32_t c1 = (uint32_t)(int)rintf(fminf(fmaxf(m1 * 0.5f, 0.f), 3.f));
    uint32_t pk = c0 | (c1 << 8);   // 2 couts -> 2 bytes

    uint32_t other = __shfl_xor_sync(0xFFFFFFFFu, pk, 1);
    if ((pair & 1) == 0) {
        uint32_t word = (pk & 0xFFFFu) | (other << 16);
        int kpl = pair >> 1;        // plane 0: co0..3, plane 1: co4..7
        out[((size_t)n * 2 + kpl) * 102400 + (size_t)(py0 + ty) * 320 + (px0 + tx)] = word;
    }
}

// ----------------------------------------------------------------------------
// Int conv 3x3 + quant_relu + 2x2 pool. Thread = 4 conv columns (2 pooled px)
// x 4 couts. Planar in/out. Weight word reused across 4 columns.
// ----------------------------------------------------------------------------
template <int CIN>
__global__ __launch_bounds__(128) void convpool2(const uint32_t* __restrict__ in,
                                                 const int8_t* __restrict__ wq,
                                                 int sidx, uint32_t* __restrict__ out,
                                                 int S, int outW4) {
    constexpr int W4 = CIN / 4;
    __shared__ int ws[4 * 9 * W4];
    const int* wg = (const int*)wq + blockIdx.z * (4 * 9 * W4);
    for (int i = threadIdx.x; i < 4 * 9 * W4; i += 128) ws[i] = wg[i];
    __syncthreads();

    const int P = S >> 1, Ph = P >> 1, HW = S * S;
    int p = blockIdx.x * 128 + threadIdx.x;
    if (p >= P * Ph) return;
    int py = p / Ph, pxp = p % Ph;
    int n = blockIdx.y;

    int acc[2][4][4] = {};
    const uint32_t* base = in + (size_t)n * W4 * HW;

#pragma unroll
    for (int r = 0; r < 4; r++) {
        int y = 2 * py + r - 1;
        if ((unsigned)y >= (unsigned)S) continue;
#pragma unroll
        for (int k = 0; k < W4; k++) {
            const uint32_t* rp = base + k * HW + y * S;
            int a[6];
#pragma unroll
            for (int c = 0; c < 6; c++) {
                int xx = 4 * pxp - 1 + c;
                a[c] = ((unsigned)xx < (unsigned)S) ? (int)__ldg(rp + xx) : 0;
            }
#pragma unroll
            for (int ky = 0; ky < 3; ky++) {
                int dy = r - ky;
                if (dy < 0 || dy > 1) continue;
#pragma unroll
                for (int kx = 0; kx < 3; kx++) {
#pragma unroll
                    for (int co = 0; co < 4; co++) {
                        int w = ws[(co * 9 + ky * 3 + kx) * W4 + k];
#pragma unroll
                        for (int j = 0; j < 4; j++)
                            acc[dy][j][co] = __dp4a(a[j + kx], w, acc[dy][j][co]);
                    }
                }
            }
        }
    }

    float s = g_scale[sidx];
    uint32_t w0 = 0, w1 = 0;
#pragma unroll
    for (int co = 0; co < 4; co++) {
        int m0 = max(max(acc[0][0][co], acc[0][1][co]),
                     max(acc[1][0][co], acc[1][1][co]));
        int m1 = max(max(acc[0][2][co], acc[0][3][co]),
                     max(acc[1][2][co], acc[1][3][co]));
        w0 |= ((uint32_t)(int)rintf(fminf(fmaxf(s * (float)m0, 0.f), 3.f))) << (co * 8);
        w1 |= ((uint32_t)(int)rintf(fminf(fmaxf(s * (float)m1, 0.f), 3.f))) << (co * 8);
    }
    uint32_t* op = out + ((size_t)n * outW4 + blockIdx.z) * (P * P) + py * P + 2 * pxp;
    op[0] = w0;
    op[1] = w1;
}

// ----------------------------------------------------------------------------
// Int conv 3x3 on 20x20 (no pool). Thread = 4 columns x NCO couts, planar.
// ----------------------------------------------------------------------------
template <int CIN, int NCO>
__global__ __launch_bounds__(128) void conv3s(const uint32_t* __restrict__ in,
                                              const int8_t* __restrict__ wq,
                                              int sidx, uint32_t* __restrict__ out,
                                              int outW4) {
    constexpr int W4 = CIN / 4;
    __shared__ int ws[NCO * 9 * W4];
    const int* wg = (const int*)wq + blockIdx.z * (NCO * 9 * W4);
    for (int i = threadIdx.x; i < NCO * 9 * W4; i += 128) ws[i] = wg[i];
    __syncthreads();

    int t = threadIdx.x;
    if (t >= 100) return;
    int py = t / 5, px0 = (t % 5) * 4;
    int n = blockIdx.y;

    int acc[4][NCO];
#pragma unroll
    for (int j = 0; j < 4; j++)
#pragma unroll
        for (int co = 0; co < NCO; co++) acc[j][co] = 0;

    const uint32_t* base = in + (size_t)n * W4 * 400;

#pragma unroll
    for (int ky = 0; ky < 3; ky++) {
        int y = py + ky - 1;
        if ((unsigned)y >= 20u) continue;
        for (int k = 0; k < W4; k++) {
            const uint32_t* rp = base + k * 400 + y * 20;
            int a[6];
#pragma unroll
            for (int c = 0; c < 6; c++) {
                int xx = px0 - 1 + c;
                a[c] = ((unsigned)xx < 20u) ? (int)__ldg(rp + xx) : 0;
            }
#pragma unroll
            for (int kx = 0; kx < 3; kx++) {
#pragma unroll
                for (int co = 0; co < NCO; co++) {
                    int w = ws[(co * 9 + ky * 3 + kx) * W4 + k];
#pragma unroll
                    for (int j = 0; j < 4; j++)
                        acc[j][co] = __dp4a(a[j + kx], w, acc[j][co]);
                }
            }
        }
    }

    float s = g_scale[sidx];
#pragma unroll
    for (int wg4 = 0; wg4 < NCO / 4; wg4++) {
        uint32_t v[4];
#pragma unroll
        for (int j = 0; j < 4; j++) {
            uint32_t b = 0;
#pragma unroll
            for (int co = 0; co < 4; co++) {
                int cc = wg4 * 4 + co;
                b |= ((uint32_t)(int)rintf(fminf(fmaxf(s * (float)acc[j][cc], 0.f), 3.f)))
                     << (co * 8);
            }
            v[j] = b;
        }
        int plane = blockIdx.z * (NCO / 4) + wg4;
        *(uint4*)(out + ((size_t)n * outW4 + plane) * 400 + py * 20 + px0) =
            make_uint4(v[0], v[1], v[2], v[3]);
    }
}

// ----------------------------------------------------------------------------
// Int conv 1x1 on 20x20. Thread = 4 pixels x 8 couts, planar.
// ----------------------------------------------------------------------------
template <int CIN>
__global__ __launch_bounds__(128) void conv1x1s(const uint32_t* __restrict__ in,
                                                const int8_t* __restrict__ wq,
                                                int sidx, uint32_t* __restrict__ out,
                                                int outW4) {
    constexpr int W4 = CIN / 4;
    __shared__ int ws[8 * W4];
    const int* wg = (const int*)wq + blockIdx.z * (8 * W4);
    for (int i = threadIdx.x; i < 8 * W4; i += 128) ws[i] = wg[i];
    __syncthreads();

    int t = threadIdx.x;
    if (t >= 100) return;
    int p0 = t * 4;
    int n = blockIdx.y;

    int acc[4][8];
#pragma unroll
    for (int j = 0; j < 4; j++)
#pragma unroll
        for (int co = 0; co < 8; co++) acc[j][co] = 0;

    const uint32_t* base = in + (size_t)n * W4 * 400;
#pragma unroll
    for (int k = 0; k < W4; k++) {
        uint4 av = __ldg((const uint4*)(base + k * 400 + p0));
        int a[4] = {(int)av.x, (int)av.y, (int)av.z, (int)av.w};
#pragma unroll
        for (int co = 0; co < 8; co++) {
            int w = ws[co * W4 + k];
#pragma unroll
            for (int j = 0; j < 4; j++)
                acc[j][co] = __dp4a(a[j], w, acc[j][co]);
        }
    }

    float s = g_scale[sidx];
#pragma unroll
    for (int wg4 = 0; wg4 < 2; wg4++) {
        uint32_t v[4];
#pragma unroll
        for (int j = 0; j < 4; j++) {
            uint32_t b = 0;
#pragma unroll
            for (int co = 0; co < 4; co++) {
                int cc = wg4 * 4 + co;
                b |= ((uint32_t)(int)rintf(fminf(fmaxf(s * (float)acc[j][cc], 0.f), 3.f)))
                     << (co * 8);
            }
            v[j] = b;
        }
        int plane = blockIdx.z * 2 + wg4;
        *(uint4*)(out + ((size_t)n * outW4 + plane) * 400 + p0) =
            make_uint4(v[0], v[1], v[2], v[3]);
    }
}

// ----------------------------------------------------------------------------
// Layer 10: int conv 3x3 104->30 + quant_hardtanh, fp32 NCHW out.
// Thread = 4 pixels x 6 couts (z = 5 groups).
// ----------------------------------------------------------------------------
__global__ __launch_bounds__(128) void conv10_out(const uint32_t* __restrict__ in,
                                                  const int8_t* __restrict__ wq,
                                                  float* __restrict__ out) {
    constexpr int W4 = 26;
    __shared__ int ws[6 * 9 * W4];
    const int* wg = (const int*)wq + blockIdx.z * (6 * 9 * W4);
    for (int i = threadIdx.x; i < 6 * 9 * W4; i += 128) ws[i] = wg[i];
    __syncthreads();

    int t = threadIdx.x;
    if (t >= 100) return;
    int py = t / 5, px0 = (t % 5) * 4;
    int n = blockIdx.y;

    int acc[4][6];
#pragma unroll
    for (int j = 0; j < 4; j++)
#pragma unroll
        for (int co = 0; co < 6; co++) acc[j][co] = 0;

    const uint32_t* base = in + (size_t)n * W4 * 400;
#pragma unroll
    for (int ky = 0; ky < 3; ky++) {
        int y = py + ky - 1;
        if ((unsigned)y >= 20u) continue;
        for (int k = 0; k < W4; k++) {
            const uint32_t* rp = base + k * 400 + y * 20;
            int a[6];
#pragma unroll
            for (int c = 0; c < 6; c++) {
                int xx = px0 - 1 + c;
                a[c] = ((unsigned)xx < 20u) ? (int)__ldg(rp + xx) : 0;
            }
#pragma unroll
            for (int kx = 0; kx < 3; kx++) {
#pragma unroll
                for (int co = 0; co < 6; co++) {
                    int w = ws[(co * 9 + ky * 3 + kx) * W4 + k];
#pragma unroll
                    for (int j = 0; j < 4; j++)
                        acc[j][co] = __dp4a(a[j + kx], w, acc[j][co]);
                }
            }
        }
    }

    float s = g_scale[9];
#pragma unroll
    for (int co = 0; co < 6; co++) {
        float4 v;
        float* vp = (float*)&v;
#pragma unroll
        for (int j = 0; j < 4; j++) {
            float x = 2.f * s * (float)acc[j][co];
            float tt = fminf(fmaxf(x, 0.f), 1.f);
            vp[j] = rintf(tt * 255.f) * (1.f / 255.f);
        }
        int cg = blockIdx.z * 6 + co;
        *(float4*)(out + ((size_t)(n * 30 + cg)) * 400 + py * 20 + px0) = v;
    }
}

// ----------------------------------------------------------------------------
// Launch
// ----------------------------------------------------------------------------
extern "C" void kernel_launch(void* const* d_in, const int* in_sizes, int n_in,
                              void* d_out, int out_size) {
    const float* x = (const float*)d_in[0];
    const float* w[10];
    for (int i = 0; i < 10; i++) w[i] = (const float*)d_in[1 + i];

    void *p_w2, *p_w3, *p_w4, *p_w5, *p_w6, *p_w7, *p_w8, *p_w9, *p_w10;
    void *p_a1, *p_a2, *p_a3, *p_a4, *p_a5, *p_a6, *p_a7, *p_a8, *p_a9;
    cudaGetSymbolAddress(&p_w2, g_w2q);
    cudaGetSymbolAddress(&p_w3, g_w3q);
    cudaGetSymbolAddress(&p_w4, g_w4q);
    cudaGetSymbolAddress(&p_w5, g_w5q);
    cudaGetSymbolAddress(&p_w6, g_w6q);
    cudaGetSymbolAddress(&p_w7, g_w7q);
    cudaGetSymbolAddress(&p_w8, g_w8q);
    cudaGetSymbolAddress(&p_w9, g_w9q);
    cudaGetSymbolAddress(&p_w10, g_w10q);
    cudaGetSymbolAddress(&p_a1, g_act1);
    cudaGetSymbolAddress(&p_a2, g_act2);
    cudaGetSymbolAddress(&p_a3, g_act3);
    cudaGetSymbolAddress(&p_a4, g_act4);
    cudaGetSymbolAddress(&p_a5, g_act5);
    cudaGetSymbolAddress(&p_a6, g_act6);
    cudaGetSymbolAddress(&p_a7, g_act7);
    cudaGetSymbolAddress(&p_a8, g_act8);
    cudaGetSymbolAddress(&p_a9, g_act9);

    const uint32_t *a1 = (const uint32_t*)p_a1, *a2 = (const uint32_t*)p_a2,
                   *a3 = (const uint32_t*)p_a3, *a4 = (const uint32_t*)p_a4,
                   *a5 = (const uint32_t*)p_a5, *a6 = (const uint32_t*)p_a6,
                   *a7 = (const uint32_t*)p_a7, *a8 = (const uint32_t*)p_a8,
                   *a9 = (const uint32_t*)p_a9;

    prep_all<<<10, 1024>>>(w[0], w[1], w[2], w[3], w[4], w[5], w[6], w[7], w[8], w[9]);

    conv1_pool<<<dim3(20, 80, 16), 256>>>(x, (uint32_t*)p_a1);

    convpool2<8><<<dim3(100, 16, 2), 128>>>(a1, (const int8_t*)p_w2, 1,
                                            (uint32_t*)p_a2, 320, 2);
    convpool2<8><<<dim3(25, 16, 4), 128>>>(a2, (const int8_t*)p_w3, 2,
                                           (uint32_t*)p_a3, 160, 4);
    convpool2<16><<<dim3(7, 16, 8), 128>>>(a3, (const int8_t*)p_w4, 3,
                                           (uint32_t*)p_a4, 80, 8);
    convpool2<32><<<dim3(2, 16, 14), 128>>>(a4, (const int8_t*)p_w5, 4,
                                            (uint32_t*)p_a5, 40, 14);
    conv3s<56, 8><<<dim3(1, 16, 13), 128>>>(a5, (const int8_t*)p_w6, 5,
                                            (uint32_t*)p_a6, 26);
    conv3s<104, 8><<<dim3(1, 16, 26), 128>>>(a6, (const int8_t*)p_w7, 6,
                                             (uint32_t*)p_a7, 52);
    conv1x1s<208><<<dim3(1, 16, 7), 128>>>(a7, (const int8_t*)p_w8, 7,
                                           (uint32_t*)p_a8, 14);
    conv3s<56, 8><<<dim3(1, 16, 13), 128>>>(a8, (const int8_t*)p_w9, 8,
                                            (uint32_t*)p_a9, 26);
    conv10_out<<<dim3(1, 16, 5), 128>>>(a9, (const int8_t*)p_w10, (float*)d_out);
}

// round 4
// speedup vs baseline: 1.9146x; 1.1521x over previous
#include <cuda_runtime.h>
#include <cstdint>

// ============================================================================
// QuantizedYOLOv3Tiny — round 4
// - prep split: absmax (parallel small) + wide grid-stride repack
// - conv1: smem tile stored as duplicated f32x2 (ULL) -> LDS.64 feeds FFMA2
//   directly, no packdup MOVs
// - 20x20 layers: NCO halved, z doubled (2x thread parallelism)
// ============================================================================

#define ALIGN16 __align__(16)

__device__ float g_scale[10];

__device__ ALIGN16 float  g_w1q[216];      // layer1: tern*s, [tap][ci][co]
__device__ ALIGN16 int8_t g_w2q[576];
__device__ ALIGN16 int8_t g_w3q[1152];
__device__ ALIGN16 int8_t g_w4q[4608];
__device__ ALIGN16 int8_t g_w5q[16128];
__device__ ALIGN16 int8_t g_w6q[52416];
__device__ ALIGN16 int8_t g_w7q[194688];
__device__ ALIGN16 int8_t g_w8q[11648];
__device__ ALIGN16 int8_t g_w9q[52416];
__device__ ALIGN16 int8_t g_w10q[28080];

__device__ ALIGN16 uint32_t g_act1[16*2*320*320];
__device__ ALIGN16 uint32_t g_act2[16*2*160*160];
__device__ ALIGN16 uint32_t g_act3[16*4*80*80];
__device__ ALIGN16 uint32_t g_act4[16*8*40*40];
__device__ ALIGN16 uint32_t g_act5[16*14*20*20];
__device__ ALIGN16 uint32_t g_act6[16*26*20*20];
__device__ ALIGN16 uint32_t g_act7[16*52*20*20];
__device__ ALIGN16 uint32_t g_act8[16*14*20*20];
__device__ ALIGN16 uint32_t g_act9[16*26*20*20];

// ----------------------------------------------------------------------------
// absmax per layer (block L)
// ----------------------------------------------------------------------------
__global__ void absmax10(const float* w0, const float* w1, const float* w2,
                         const float* w3, const float* w4, const float* w5,
                         const float* w6, const float* w7, const float* w8,
                         const float* w9) {
    const float* ws[10] = {w0,w1,w2,w3,w4,w5,w6,w7,w8,w9};
    const int    ns[10] = {216,576,1152,4608,16128,52416,194688,11648,52416,28080};
    int L = blockIdx.x;
    const float* w = ws[L];
    int n = ns[L];
    int tid = threadIdx.x;

    float m = 0.f;
    const float4* w4p = (const float4*)w;
    int n4 = n >> 2;
    for (int i = tid; i < n4; i += blockDim.x) {
        float4 v = w4p[i];
        m = fmaxf(m, fmaxf(fmaxf(fabsf(v.x), fabsf(v.y)),
                           fmaxf(fabsf(v.z), fabsf(v.w))));
    }
    __shared__ float red[256];
    red[tid] = m;
    __syncthreads();
    for (int s = 128; s > 0; s >>= 1) {
        if (tid < s) red[tid] = fmaxf(red[tid], red[tid + s]);
        __syncthreads();
    }
    if (tid == 0) g_scale[L] = fmaxf(red[0], 1e-8f);
}

// ----------------------------------------------------------------------------
// Wide repack: grid-strided over all 361928 weights, 10 layers.
// ----------------------------------------------------------------------------
__global__ void repack_all(const float* w0, const float* w1, const float* w2,
                           const float* w3, const float* w4, const float* w5,
                           const float* w6, const float* w7, const float* w8,
                           const float* w9) {
    const float* ws[10] = {w0,w1,w2,w3,w4,w5,w6,w7,w8,w9};
    const int    ns[10] = {216,576,1152,4608,16128,52416,194688,11648,52416,28080};
    const int  cins[10] = {3,8,8,16,32,56,104,208,56,104};
    const int   kks[10] = {9,9,9,9,9,9,9,1,9,9};
    int8_t* wqs[10] = {nullptr, g_w2q, g_w3q, g_w4q, g_w5q, g_w6q,
                       g_w7q, g_w8q, g_w9q, g_w10q};

    int gid = blockIdx.x * blockDim.x + threadIdx.x;
    // locate layer
    int L = 0, off = gid;
    while (L < 10 && off >= ns[L]) { off -= ns[L]; L++; }
    if (L >= 10) return;

    float s = g_scale[L];
    const float* w = ws[L];
    if (L == 0) {
        int co = off / 27, rem = off % 27, ci = rem / 9, t = rem % 9;
        float v = w[off] / s;
        float q = rintf(fminf(fmaxf(v, -1.f), 1.f));
        g_w1q[(t * 3 + ci) * 8 + co] = q * s;
    } else {
        int cin = cins[L], kk = kks[L];
        int co = off / (cin * kk);
        int rem = off % (cin * kk);
        int ci = rem / kk;
        int t  = rem % kk;
        float v = w[off] / s;
        int q = (int)rintf(fminf(fmaxf(v, -1.f), 1.f));
        wqs[L][(co * kk + t) * cin + ci] = (int8_t)q;
    }
}

// ----------------------------------------------------------------------------
// f32x2 helpers
// ----------------------------------------------------------------------------
__device__ __forceinline__ void ffma2(unsigned long long& d,
                                      unsigned long long a,
                                      unsigned long long b) {
    asm("fma.rn.f32x2 %0, %1, %2, %0;" : "+l"(d) : "l"(a), "l"(b));
}
__device__ __forceinline__ void unpack2(unsigned long long v, float& lo, float& hi) {
    uint32_t a, b;
    asm("mov.b64 {%0, %1}, %2;" : "=r"(a), "=r"(b) : "l"(v));
    lo = __uint_as_float(a);
    hi = __uint_as_float(b);
}

// ----------------------------------------------------------------------------
// Layer 1: float conv 3->8 @640x640 + quant_relu + 2x2 pool -> planar codes.
// smem tile holds duplicated {v,v} 64-bit words -> LDS.64 feeds FFMA2 directly.
// 256 threads = 64 pooled pixels (16x4) x 4 cout-pairs.
// ----------------------------------------------------------------------------
__global__ __launch_bounds__(256) void conv1_pool(const float* __restrict__ x,
                                                  uint32_t* __restrict__ out) {
    __shared__ unsigned long long s_in[3][10][34];   // 8160 B

    const int tid = threadIdx.x;
    const int pair = tid & 3;
    const int q = tid >> 2;
    const int tx = q & 15, ty = q >> 4;
    const int n = blockIdx.z;
    const int px0 = blockIdx.x * 16, py0 = blockIdx.y * 4;

    for (int i = tid; i < 3 * 10 * 34; i += 256) {
        int ch = i / 340, rem = i % 340, row = rem / 34, col = rem % 34;
        int gx = 2 * px0 - 1 + col;
        int gy = 2 * py0 - 1 + row;
        float v = 0.f;
        if ((unsigned)gx < 640u && (unsigned)gy < 640u)
            v = __ldg(x + ((size_t)(n * 3 + ch) * 640 + gy) * 640 + gx);
        uint32_t b = __float_as_uint(v);
        s_in[ch][row][col] = ((unsigned long long)b << 32) | b;
    }

    unsigned long long wreg[27];
    const unsigned long long* wsrc = (const unsigned long long*)g_w1q;
#pragma unroll
    for (int i = 0; i < 27; i++) wreg[i] = wsrc[i * 4 + pair];

    __syncthreads();

    unsigned long long acc[2][2] = {{0ull, 0ull}, {0ull, 0ull}};

#pragma unroll
    for (int r = 0; r < 4; r++) {
#pragma unroll
        for (int c = 0; c < 4; c++) {
            int row = 2 * ty + r, col = 2 * tx + c;
            unsigned long long vv0 = s_in[0][row][col];
            unsigned long long vv1 = s_in[1][row][col];
            unsigned long long vv2 = s_in[2][row][col];
#pragma unroll
            for (int dy = 0; dy < 2; dy++) {
                int ky = r - dy;
                if (ky < 0 || ky > 2) continue;
#pragma unroll
                for (int dx = 0; dx < 2; dx++) {
                    int kx = c - dx;
                    if (kx < 0 || kx > 2) continue;
                    int tap = ky * 3 + kx;
                    ffma2(acc[dy][dx], vv0, wreg[tap * 3 + 0]);
                    ffma2(acc[dy][dx], vv1, wreg[tap * 3 + 1]);
                    ffma2(acc[dy][dx], vv2, wreg[tap * 3 + 2]);
                }
            }
        }
    }

    float l00, h00, l01, h01, l10, h10, l11, h11;
    unpack2(acc[0][0], l00, h00);
    unpack2(acc[0][1], l01, h01);
    unpack2(acc[1][0], l10, h10);
    unpack2(acc[1][1], l11, h11);
    float m0 = fmaxf(fmaxf(l00, l01), fmaxf(l10, l11));
    float m1 = fmaxf(fmaxf(h00, h01), fmaxf(h10, h11));
    uint32_t c0 = (uint32_t)(int)rintf(fminf(fmaxf(m0 * 0.5f, 0.f), 3.f));
    uint32_t c1 = (uint32_t)(int)rintf(fminf(fmaxf(m1 * 0.5f, 0.f), 3.f));
    uint32_t pk = c0 | (c1 << 8);

    uint32_t other = __shfl_xor_sync(0xFFFFFFFFu, pk, 1);
    if ((pair & 1) == 0) {
        uint32_t word = (pk & 0xFFFFu) | (other << 16);
        int kpl = pair >> 1;
        out[((size_t)n * 2 + kpl) * 102400 + (size_t)(py0 + ty) * 320 + (px0 + tx)] = word;
    }
}

// ----------------------------------------------------------------------------
// Int conv 3x3 + quant_relu + 2x2 pool. Thread = 4 conv columns x 4 couts.
// ----------------------------------------------------------------------------
template <int CIN>
__global__ __launch_bounds__(128) void convpool2(const uint32_t* __restrict__ in,
                                                 const int8_t* __restrict__ wq,
                                                 int sidx, uint32_t* __restrict__ out,
                                                 int S, int outW4) {
    constexpr int W4 = CIN / 4;
    __shared__ int ws[4 * 9 * W4];
    const int* wg = (const int*)wq + blockIdx.z * (4 * 9 * W4);
    for (int i = threadIdx.x; i < 4 * 9 * W4; i += 128) ws[i] = wg[i];
    __syncthreads();

    const int P = S >> 1, Ph = P >> 1, HW = S * S;
    int p = blockIdx.x * 128 + threadIdx.x;
    if (p >= P * Ph) return;
    int py = p / Ph, pxp = p % Ph;
    int n = blockIdx.y;

    int acc[2][4][4] = {};
    const uint32_t* base = in + (size_t)n * W4 * HW;

#pragma unroll
    for (int r = 0; r < 4; r++) {
        int y = 2 * py + r - 1;
        if ((unsigned)y >= (unsigned)S) continue;
#pragma unroll
        for (int k = 0; k < W4; k++) {
            const uint32_t* rp = base + k * HW + y * S;
            int a[6];
#pragma unroll
            for (int c = 0; c < 6; c++) {
                int xx = 4 * pxp - 1 + c;
                a[c] = ((unsigned)xx < (unsigned)S) ? (int)__ldg(rp + xx) : 0;
            }
#pragma unroll
            for (int ky = 0; ky < 3; ky++) {
                int dy = r - ky;
                if (dy < 0 || dy > 1) continue;
#pragma unroll
                for (int kx = 0; kx < 3; kx++) {
#pragma unroll
                    for (int co = 0; co < 4; co++) {
                        int w = ws[(co * 9 + ky * 3 + kx) * W4 + k];
#pragma unroll
                        for (int j = 0; j < 4; j++)
                            acc[dy][j][co] = __dp4a(a[j + kx], w, acc[dy][j][co]);
                    }
                }
            }
        }
    }

    float s = g_scale[sidx];
    uint32_t w0 = 0, w1 = 0;
#pragma unroll
    for (int co = 0; co < 4; co++) {
        int m0 = max(max(acc[0][0][co], acc[0][1][co]),
                     max(acc[1][0][co], acc[1][1][co]));
        int m1 = max(max(acc[0][2][co], acc[0][3][co]),
                     max(acc[1][2][co], acc[1][3][co]));
        w0 |= ((uint32_t)(int)rintf(fminf(fmaxf(s * (float)m0, 0.f), 3.f))) << (co * 8);
        w1 |= ((uint32_t)(int)rintf(fminf(fmaxf(s * (float)m1, 0.f), 3.f))) << (co * 8);
    }
    uint32_t* op = out + ((size_t)n * outW4 + blockIdx.z) * (P * P) + py * P + 2 * pxp;
    op[0] = w0;
    op[1] = w1;
}

// ----------------------------------------------------------------------------
// Int conv 3x3 on 20x20 (no pool). Thread = 4 columns x NCO couts.
// ----------------------------------------------------------------------------
template <int CIN, int NCO>
__global__ __launch_bounds__(128) void conv3s(const uint32_t* __restrict__ in,
                                              const int8_t* __restrict__ wq,
                                              int sidx, uint32_t* __restrict__ out,
                                              int outW4) {
    constexpr int W4 = CIN / 4;
    __shared__ int ws[NCO * 9 * W4];
    const int* wg = (const int*)wq + blockIdx.z * (NCO * 9 * W4);
    for (int i = threadIdx.x; i < NCO * 9 * W4; i += 128) ws[i] = wg[i];
    __syncthreads();

    int t = threadIdx.x;
    if (t >= 100) return;
    int py = t / 5, px0 = (t % 5) * 4;
    int n = blockIdx.y;

    int acc[4][NCO];
#pragma unroll
    for (int j = 0; j < 4; j++)
#pragma unroll
        for (int co = 0; co < NCO; co++) acc[j][co] = 0;

    const uint32_t* base = in + (size_t)n * W4 * 400;

#pragma unroll
    for (int ky = 0; ky < 3; ky++) {
        int y = py + ky - 1;
        if ((unsigned)y >= 20u) continue;
        for (int k = 0; k < W4; k++) {
            const uint32_t* rp = base + k * 400 + y * 20;
            int a[6];
#pragma unroll
            for (int c = 0; c < 6; c++) {
                int xx = px0 - 1 + c;
                a[c] = ((unsigned)xx < 20u) ? (int)__ldg(rp + xx) : 0;
            }
#pragma unroll
            for (int kx = 0; kx < 3; kx++) {
#pragma unroll
                for (int co = 0; co < NCO; co++) {
                    int w = ws[(co * 9 + ky * 3 + kx) * W4 + k];
#pragma unroll
                    for (int j = 0; j < 4; j++)
                        acc[j][co] = __dp4a(a[j + kx], w, acc[j][co]);
                }
            }
        }
    }

    float s = g_scale[sidx];
#pragma unroll
    for (int wg4 = 0; wg4 < NCO / 4; wg4++) {
        uint32_t v[4];
#pragma unroll
        for (int j = 0; j < 4; j++) {
            uint32_t b = 0;
#pragma unroll
            for (int co = 0; co < 4; co++) {
                int cc = wg4 * 4 + co;
                b |= ((uint32_t)(int)rintf(fminf(fmaxf(s * (float)acc[j][cc], 0.f), 3.f)))
                     << (co * 8);
            }
            v[j] = b;
        }
        int plane = blockIdx.z * (NCO / 4) + wg4;
        *(uint4*)(out + ((size_t)n * outW4 + plane) * 400 + py * 20 + px0) =
            make_uint4(v[0], v[1], v[2], v[3]);
    }
}

// ----------------------------------------------------------------------------
// Int conv 1x1 on 20x20. Thread = 4 pixels x NCO couts.
// ----------------------------------------------------------------------------
template <int CIN, int NCO>
__global__ __launch_bounds__(128) void conv1x1s(const uint32_t* __restrict__ in,
                                                const int8_t* __restrict__ wq,
                                                int sidx, uint32_t* __restrict__ out,
                                                int outW4) {
    constexpr int W4 = CIN / 4;
    __shared__ int ws[NCO * W4];
    const int* wg = (const int*)wq + blockIdx.z * (NCO * W4);
    for (int i = threadIdx.x; i < NCO * W4; i += 128) ws[i] = wg[i];
    __syncthreads();

    int t = threadIdx.x;
    if (t >= 100) return;
    int p0 = t * 4;
    int n = blockIdx.y;

    int acc[4][NCO];
#pragma unroll
    for (int j = 0; j < 4; j++)
#pragma unroll
        for (int co = 0; co < NCO; co++) acc[j][co] = 0;

    const uint32_t* base = in + (size_t)n * W4 * 400;
#pragma unroll
    for (int k = 0; k < W4; k++) {
        uint4 av = __ldg((const uint4*)(base + k * 400 + p0));
        int a[4] = {(int)av.x, (int)av.y, (int)av.z, (int)av.w};
#pragma unroll
        for (int co = 0; co < NCO; co++) {
            int w = ws[co * W4 + k];
#pragma unroll
            for (int j = 0; j < 4; j++)
                acc[j][co] = __dp4a(a[j], w, acc[j][co]);
        }
    }

    float s = g_scale[sidx];
#pragma unroll
    for (int wg4 = 0; wg4 < NCO / 4; wg4++) {
        uint32_t v[4];
#pragma unroll
        for (int j = 0; j < 4; j++) {
            uint32_t b = 0;
#pragma unroll
            for (int co = 0; co < 4; co++) {
                int cc = wg4 * 4 + co;
                b |= ((uint32_t)(int)rintf(fminf(fmaxf(s * (float)acc[j][cc], 0.f), 3.f)))
                     << (co * 8);
            }
            v[j] = b;
        }
        int plane = blockIdx.z * (NCO / 4) + wg4;
        *(uint4*)(out + ((size_t)n * outW4 + plane) * 400 + p0) =
            make_uint4(v[0], v[1], v[2], v[3]);
    }
}

// ----------------------------------------------------------------------------
// Layer 10: int conv 3x3 104->30 + quant_hardtanh, fp32 NCHW out.
// Thread = 4 pixels x 3 couts (z = 10 groups).
// ----------------------------------------------------------------------------
__global__ __launch_bounds__(128) void conv10_out(const uint32_t* __restrict__ in,
                                                  const int8_t* __restrict__ wq,
                                                  float* __restrict__ out) {
    constexpr int W4 = 26;
    __shared__ int ws[3 * 9 * W4];
    const int* wg = (const int*)wq + blockIdx.z * (3 * 9 * W4);
    for (int i = threadIdx.x; i < 3 * 9 * W4; i += 128) ws[i] = wg[i];
    __syncthreads();

    int t = threadIdx.x;
    if (t >= 100) return;
    int py = t / 5, px0 = (t % 5) * 4;
    int n = blockIdx.y;

    int acc[4][3];
#pragma unroll
    for (int j = 0; j < 4; j++)
#pragma unroll
        for (int co = 0; co < 3; co++) acc[j][co] = 0;

    const uint32_t* base = in + (size_t)n * W4 * 400;
#pragma unroll
    for (int ky = 0; ky < 3; ky++) {
        int y = py + ky - 1;
        if ((unsigned)y >= 20u) continue;
        for (int k = 0; k < W4; k++) {
            const uint32_t* rp = base + k * 400 + y * 20;
            int a[6];
#pragma unroll
            for (int c = 0; c < 6; c++) {
                int xx = px0 - 1 + c;
                a[c] = ((unsigned)xx < 20u) ? (int)__ldg(rp + xx) : 0;
            }
#pragma unroll
            for (int kx = 0; kx < 3; kx++) {
#pragma unroll
                for (int co = 0; co < 3; co++) {
                    int w = ws[(co * 9 + ky * 3 + kx) * W4 + k];
#pragma unroll
                    for (int j = 0; j < 4; j++)
                        acc[j][co] = __dp4a(a[j + kx], w, acc[j][co]);
                }
            }
        }
    }

    float s = g_scale[9];
#pragma unroll
    for (int co = 0; co < 3; co++) {
        float4 v;
        float* vp = (float*)&v;
#pragma unroll
        for (int j = 0; j < 4; j++) {
            float x = 2.f * s * (float)acc[j][co];
            float tt = fminf(fmaxf(x, 0.f), 1.f);
            vp[j] = rintf(tt * 255.f) * (1.f / 255.f);
        }
        int cg = blockIdx.z * 3 + co;
        *(float4*)(out + ((size_t)(n * 30 + cg)) * 400 + py * 20 + px0) = v;
    }
}

// ----------------------------------------------------------------------------
// Launch
// ----------------------------------------------------------------------------
extern "C" void kernel_launch(void* const* d_in, const int* in_sizes, int n_in,
                              void* d_out, int out_size) {
    const float* x = (const float*)d_in[0];
    const float* w[10];
    for (int i = 0; i < 10; i++) w[i] = (const float*)d_in[1 + i];

    void *p_w2, *p_w3, *p_w4, *p_w5, *p_w6, *p_w7, *p_w8, *p_w9, *p_w10;
    void *p_a1, *p_a2, *p_a3, *p_a4, *p_a5, *p_a6, *p_a7, *p_a8, *p_a9;
    cudaGetSymbolAddress(&p_w2, g_w2q);
    cudaGetSymbolAddress(&p_w3, g_w3q);
    cudaGetSymbolAddress(&p_w4, g_w4q);
    cudaGetSymbolAddress(&p_w5, g_w5q);
    cudaGetSymbolAddress(&p_w6, g_w6q);
    cudaGetSymbolAddress(&p_w7, g_w7q);
    cudaGetSymbolAddress(&p_w8, g_w8q);
    cudaGetSymbolAddress(&p_w9, g_w9q);
    cudaGetSymbolAddress(&p_w10, g_w10q);
    cudaGetSymbolAddress(&p_a1, g_act1);
    cudaGetSymbolAddress(&p_a2, g_act2);
    cudaGetSymbolAddress(&p_a3, g_act3);
    cudaGetSymbolAddress(&p_a4, g_act4);
    cudaGetSymbolAddress(&p_a5, g_act5);
    cudaGetSymbolAddress(&p_a6, g_act6);
    cudaGetSymbolAddress(&p_a7, g_act7);
    cudaGetSymbolAddress(&p_a8, g_act8);
    cudaGetSymbolAddress(&p_a9, g_act9);

    const uint32_t *a1 = (const uint32_t*)p_a1, *a2 = (const uint32_t*)p_a2,
                   *a3 = (const uint32_t*)p_a3, *a4 = (const uint32_t*)p_a4,
                   *a5 = (const uint32_t*)p_a5, *a6 = (const uint32_t*)p_a6,
                   *a7 = (const uint32_t*)p_a7, *a8 = (const uint32_t*)p_a8,
                   *a9 = (const uint32_t*)p_a9;

    absmax10<<<10, 256>>>(w[0], w[1], w[2], w[3], w[4], w[5], w[6], w[7], w[8], w[9]);
    repack_all<<<1415, 256>>>(w[0], w[1], w[2], w[3], w[4], w[5], w[6], w[7], w[8], w[9]);

    conv1_pool<<<dim3(20, 80, 16), 256>>>(x, (uint32_t*)p_a1);

    convpool2<8><<<dim3(100, 16, 2), 128>>>(a1, (const int8_t*)p_w2, 1,
                                            (uint32_t*)p_a2, 320, 2);
    convpool2<8><<<dim3(25, 16, 4), 128>>>(a2, (const int8_t*)p_w3, 2,
                                           (uint32_t*)p_a3, 160, 4);
    convpool2<16><<<dim3(7, 16, 8), 128>>>(a3, (const int8_t*)p_w4, 3,
                                           (uint32_t*)p_a4, 80, 8);
    convpool2<32><<<dim3(2, 16, 14), 128>>>(a4, (const int8_t*)p_w5, 4,
                                            (uint32_t*)p_a5, 40, 14);
    conv3s<56, 4><<<dim3(1, 16, 26), 128>>>(a5, (const int8_t*)p_w6, 5,
                                            (uint32_t*)p_a6, 26);
    conv3s<104, 4><<<dim3(1, 16, 52), 128>>>(a6, (const int8_t*)p_w7, 6,
                                             (uint32_t*)p_a7, 52);
    conv1x1s<208, 4><<<dim3(1, 16, 14), 128>>>(a7, (const int8_t*)p_w8, 7,
                                               (uint32_t*)p_a8, 14);
    conv3s<56, 4><<<dim3(1, 16, 26), 128>>>(a8, (const int8_t*)p_w9, 8,
                                            (uint32_t*)p_a9, 26);
    conv10_out<<<dim3(1, 16, 10), 128>>>(a9, (const int8_t*)p_w10, (float*)d_out);
}